// round 6
// baseline (speedup 1.0000x reference)
#include <cuda_runtime.h>
#include <stdint.h>

#define T_STEPS 128
#define BATCH   64
#define IN_DIM  512
#define H       1024
#define NE      819          /* int(1024*0.8) excitatory units */
#define NL      3
#define KMAX    2048
#define KSLICE  256
#define NKC     8            /* 8 partial slices of 256 k each */
#define NBLOCKS 128
#define NTHREADS 256
#define ALPHA   0.2f

// dynamic smem: 16KB activation/transpose buffer + 192KB resident weights
#define XS_FLOATS   4096                       /* 64k x 64b chunk */
#define WS_FLOATS   (NL * KSLICE * 64)         /* 49152 */
#define SMEM_BYTES  ((XS_FLOATS + WS_FLOATS) * 4)   /* 212992 */

// ---------------- device scratch (static, allocation-free) ----------------
__device__ float g_Wc[NL * KMAX * H + 16 * H];   // combined |W| w/ Dale sign, [j][k][i]
__device__ float g_xinT[T_STEPS * IN_DIM * BATCH]; // inputs transposed [t][k][b]
__device__ float g_h [NL * H * BATCH];           // raw hidden, [j][k][b]
__device__ float g_hm[NL * H * BATCH];           // e-masked hidden, [j][k][b]
__device__ float g_v [NL * BATCH * H];           // leaky state, [j][b][n]
__device__ float g_part[NKC * BATCH * H];        // split-K partials [kc][b][n]
__device__ volatile unsigned g_slots[NBLOCKS];   // flat barrier slots

// ---------------- helpers ----------------
__device__ __forceinline__ unsigned long long pack2(float f) {
    unsigned long long r; unsigned u = __float_as_uint(f);
    asm("mov.b64 %0, {%1, %1};" : "=l"(r) : "r"(u));
    return r;
}
__device__ __forceinline__ unsigned long long fma2(unsigned long long a,
                                                   unsigned long long b,
                                                   unsigned long long c) {
    unsigned long long d;
    asm("fma.rn.f32x2 %0, %1, %2, %3;" : "=l"(d) : "l"(a), "l"(b), "l"(c));
    return d;
}

// Flat no-atomic grid barrier: each block owns one slot; warp0 polls all slots.
__device__ __forceinline__ void grid_sync(unsigned &gen, int bk, int w, int lane) {
    const unsigned next = gen + 1;
    __syncthreads();
    if (w == 0) {
        __threadfence();                       // publish this block's writes
        if (lane == 0) g_slots[bk] = next;     // zero-contention arrival
        const volatile unsigned* sl = g_slots + lane * 4;
        unsigned s0, s1, s2, s3;
        do {
            s0 = sl[0]; s1 = sl[1]; s2 = sl[2]; s3 = sl[3];
        } while (!__all_sync(0xffffffffu,
                 (s0 >= next) && (s1 >= next) && (s2 >= next) && (s3 >= next)));
        __threadfence();                       // acquire: invalidate stale L1
    }
    __syncthreads();
    gen = next;
}

// ---------------- preprocessing kernels ----------------
__global__ void k_prep_weights(const float* __restrict__ Win0,
                               const float* __restrict__ Win1,
                               const float* __restrict__ Win2,
                               const float* __restrict__ Wrec) {
    int idx = blockIdx.x * blockDim.x + threadIdx.x;
    if (idx >= NL * KMAX * H + 16 * H) return;
    if (idx >= NL * KMAX * H) { g_Wc[idx] = 0.f; return; }
    int j = idx / (KMAX * H);
    int r = idx - j * (KMAX * H);
    int k = r >> 10;
    int i = r & (H - 1);
    float v = 0.f;
    if (j == 0) {
        if (k < IN_DIM) {
            v = fabsf(Win0[i * IN_DIM + k]);
        } else if (k < IN_DIM + H) {
            int kk = k - IN_DIM;
            v = fabsf(Wrec[(size_t)i * H + kk]);
            if (kk >= NE) v = -v;
        }
    } else {
        const float* Wi = (j == 1) ? Win1 : Win2;
        if (k < H) {
            v = fabsf(Wi[(size_t)i * H + k]);
        } else {
            int kk = k - H;
            v = fabsf(Wrec[((size_t)j * H + i) * H + kk]);
            if (kk >= NE) v = -v;
        }
    }
    g_Wc[idx] = v;
}

__global__ void k_transpose_inputs(const float* __restrict__ inputs) {
    int idx = blockIdx.x * blockDim.x + threadIdx.x;
    if (idx >= T_STEPS * IN_DIM * BATCH) return;
    int b = idx & (BATCH - 1);
    int k = (idx >> 6) & (IN_DIM - 1);
    int t = idx >> 15;
    g_xinT[idx] = inputs[((size_t)t * BATCH + b) * IN_DIM + k];
}

__global__ void k_init(const float* __restrict__ hid0, float* __restrict__ out_hid) {
    int idx = blockIdx.x * blockDim.x + threadIdx.x;
    if (idx < NBLOCKS) g_slots[idx] = 0;
    if (idx >= NL * H * BATCH) return;
    int b = idx & (BATCH - 1);
    int k = (idx >> 6) & (H - 1);
    int j = idx >> 16;
    float h0 = hid0[(size_t)b * H + k];
    g_h[idx]  = h0;
    g_hm[idx] = (k < NE) ? h0 : 0.f;
    g_v[idx]  = 0.f;
    out_hid[((size_t)j * (T_STEPS + 1) * BATCH + b) * H + k] = h0;
}

// ---------------- main persistent kernel ----------------
__global__ void __launch_bounds__(NTHREADS, 1)
k_main(const float* __restrict__ bias, float* __restrict__ out_y, float* __restrict__ out_hid) {
    extern __shared__ float smem[];
    float* xs  = smem;                 // 4096 floats: 64k x 64b activation chunk / phase-B tile
    float* w_s = smem + XS_FLOATS;     // 49152 floats: resident weights [j][256k][64n]

    const int bk   = blockIdx.x;
    const int tid  = threadIdx.x;
    const int lane = tid & 31;
    const int w    = tid >> 5;         // warp id (0..7)
    // phase A mapping: 16 neuron-groups x 8 k-chunks (256 k each)
    const int ng   = bk & 15;
    const int kc   = bk >> 4;
    const int bg   = w;                // 8 batch-groups of 8
    // phase B mapping: 32 n-tiles x 4 b-tiles
    const int n0 = (bk & 31) << 5;
    const int b0 = (bk >> 5) << 4;

    // ---- prologue: load this block's weight slice into smem (once) ----
    {
        for (int it = tid; it < NL * KSLICE * 16; it += NTHREADS) {
            int j   = it / (KSLICE * 16);
            int rem = it - j * (KSLICE * 16);
            int kk  = rem >> 4;
            int n4  = rem & 15;
            const float4 v = *reinterpret_cast<const float4*>(
                g_Wc + ((size_t)j * KMAX + (size_t)kc * KSLICE + kk) * H + ng * 64 + n4 * 4);
            *reinterpret_cast<float4*>(w_s + ((size_t)j * KSLICE + kk) * 64 + n4 * 4) = v;
        }
    }
    __syncthreads();

    unsigned gen = 0;

    for (int t = 0; t < T_STEPS; t++) {
        for (int j = 0; j < NL; j++) {
            const int nkc = (j == 0) ? 6 : 8;

            // ---------------- Phase A ----------------
            if (kc < nkc) {
                const float* xsrc;
                if (j == 0) {
                    xsrc = (kc < 2)
                         ? (g_xinT + ((size_t)t * IN_DIM + kc * KSLICE) * BATCH)
                         : (g_h    + ((size_t)(kc - 2) * KSLICE) * BATCH);
                } else {
                    xsrc = (kc < 4)
                         ? (g_hm + ((size_t)(j - 1) * H + kc * KSLICE) * BATCH)
                         : (g_h  + ((size_t)j * H + (kc - 4) * KSLICE) * BATCH);
                }
                const float4* s4 = reinterpret_cast<const float4*>(xsrc);

                float4 rbuf[4];
                #pragma unroll
                for (int i = 0; i < 4; i++) rbuf[i] = s4[tid + i * NTHREADS];  // chunk 0

                unsigned long long a0[4], a1[4];
                #pragma unroll
                for (int p = 0; p < 4; p++) { a0[p] = 0ull; a1[p] = 0ull; }

                const float* wsj = w_s + (size_t)j * KSLICE * 64 + (lane << 1);

                #pragma unroll 1
                for (int c = 0; c < 4; c++) {
                    __syncthreads();
                    {
                        float4* d4 = reinterpret_cast<float4*>(xs);
                        #pragma unroll
                        for (int i = 0; i < 4; i++) d4[tid + i * NTHREADS] = rbuf[i];
                    }
                    __syncthreads();
                    if (c < 3) {
                        #pragma unroll
                        for (int i = 0; i < 4; i++)
                            rbuf[i] = s4[(c + 1) * 1024 + tid + i * NTHREADS];
                    }
                    const float* wk = wsj + (size_t)c * 64 * 64;
                    const float* xk = xs + bg * 8;
                    #pragma unroll 4
                    for (int kk = 0; kk < 64; kk++) {
                        float2 wv = *reinterpret_cast<const float2*>(wk + (size_t)kk * 64);
                        unsigned long long w0 = pack2(wv.x);
                        unsigned long long w1 = pack2(wv.y);
                        const ulonglong2 qa = *reinterpret_cast<const ulonglong2*>(xk + (size_t)kk * 64);
                        const ulonglong2 qb = *reinterpret_cast<const ulonglong2*>(xk + (size_t)kk * 64 + 4);
                        a0[0] = fma2(qa.x, w0, a0[0]);  a1[0] = fma2(qa.x, w1, a1[0]);
                        a0[1] = fma2(qa.y, w0, a0[1]);  a1[1] = fma2(qa.y, w1, a1[1]);
                        a0[2] = fma2(qb.x, w0, a0[2]);  a1[2] = fma2(qb.x, w1, a1[2]);
                        a0[3] = fma2(qb.y, w0, a0[3]);  a1[3] = fma2(qb.y, w1, a1[3]);
                    }
                }
                // write partials: [kc][b][n], 8 x STG.64 (adjacent neuron pair)
                float* pp = g_part + ((size_t)kc * BATCH + bg * 8) * H + ng * 64 + (lane << 1);
                #pragma unroll
                for (int p = 0; p < 4; p++) {
                    uint2 u0 = *reinterpret_cast<uint2*>(&a0[p]);
                    uint2 u1 = *reinterpret_cast<uint2*>(&a1[p]);
                    float2 lo = make_float2(__uint_as_float(u0.x), __uint_as_float(u1.x));
                    float2 hi = make_float2(__uint_as_float(u0.y), __uint_as_float(u1.y));
                    *reinterpret_cast<float2*>(pp + (size_t)(2 * p)     * H) = lo;
                    *reinterpret_cast<float2*>(pp + (size_t)(2 * p + 1) * H) = hi;
                }
            }
            grid_sync(gen, bk, w, lane);

            // ---------------- Phase B: reduce + leaky/ReLU + outputs ----------------
            {
                #pragma unroll
                for (int q = 0; q < 2; q++) {
                    int b  = b0 + w + q * 8;
                    int nn = n0 + lane;
                    float s = bias[j * H + nn];
                    #pragma unroll
                    for (int c = 0; c < 8; c++)
                        if (c < nkc)
                            s += g_part[((size_t)c * BATCH + b) * H + nn];
                    size_t vidx = ((size_t)j * BATCH + b) * H + nn;
                    float v = fmaf(1.0f - ALPHA, g_v[vidx], ALPHA * s);
                    g_v[vidx] = v;
                    float h = fmaxf(v, 0.f);
                    out_hid[(((size_t)j * (T_STEPS + 1) + (t + 1)) * BATCH + b) * H + nn] = h;
                    if (j == 2)
                        out_y[((size_t)t * BATCH + b) * H + nn] = (nn < NE) ? h : 0.f;
                    xs[lane * 17 + (w + q * 8)] = h;   // padded transpose tile
                }
                __syncthreads();
                #pragma unroll
                for (int q = 0; q < 2; q++) {
                    int idx = tid + q * NTHREADS;      // 32n x 16b tile
                    int nn = idx >> 4, bb = idx & 15;
                    float h = xs[nn * 17 + bb];
                    size_t hidx = ((size_t)j * H + n0 + nn) * BATCH + b0 + bb;
                    g_h[hidx]  = h;
                    g_hm[hidx] = ((n0 + nn) < NE) ? h : 0.f;
                }
            }
            grid_sync(gen, bk, w, lane);
        }
    }
}

// ---------------- host entry ----------------
extern "C" void kernel_launch(void* const* d_in, const int* in_sizes, int n_in,
                              void* d_out, int out_size) {
    const float* inputs = (const float*)d_in[0];   // [128,64,512]
    const float* hid0   = (const float*)d_in[1];   // [1,64,1024]
    const float* Win0   = (const float*)d_in[2];   // [1024,512]
    const float* Win1   = (const float*)d_in[3];   // [1024,1024]
    const float* Win2   = (const float*)d_in[4];   // [1024,1024]
    const float* Wrec   = (const float*)d_in[5];   // [3,1024,1024]
    const float* bias   = (const float*)d_in[6];   // [3,1024]

    float* out_y   = (float*)d_out;                               // [128,64,1024]
    float* out_hid = (float*)d_out + (size_t)T_STEPS * BATCH * H; // [3,129,64,1024]

    cudaFuncSetAttribute(k_main, cudaFuncAttributeMaxDynamicSharedMemorySize, SMEM_BYTES);

    {
        int n = NL * KMAX * H + 16 * H;
        k_prep_weights<<<(n + 255) / 256, 256>>>(Win0, Win1, Win2, Wrec);
    }
    {
        int n = T_STEPS * IN_DIM * BATCH;
        k_transpose_inputs<<<(n + 255) / 256, 256>>>(inputs);
    }
    {
        int n = NL * H * BATCH;
        k_init<<<(n + 255) / 256, 256>>>(hid0, out_hid);
    }
    k_main<<<NBLOCKS, NTHREADS, SMEM_BYTES>>>(bias, out_y, out_hid);
}